// round 12
// baseline (speedup 1.0000x reference)
#include <cuda_runtime.h>

// Problem shape (fixed by setup_inputs): x: (B=4, S=4096, D=64) f32; out: (B,S) f32
#define S_LEN  4096
#define D_DIM  64
#define CH     8               // chunk size (norm elements per L1 entry)
#define NCH    (S_LEN / CH)    // 512 chunks per row
#define NB     128             // grid (co-resident: 128 <= 148 SMs)
#define NT     512             // threads per block
#define QPB    128             // queries/rows per block (32 segments per batch row)

// Device-global scratch (no allocation). Flags are MONOTONIC across graph
// replays (one producer per flag, +1 per launch; per-replay target derived
// from the producer's own flag value at entry).
__device__ float    g_norms[4 * S_LEN];     // per-(b,t) L1 norms
__device__ float    g_L1[4 * NCH];          // per-(b,chunk) 8-row minima
__device__ unsigned g_flag[4][32];          // flag[b][s]: segment s of batch b done

__device__ __forceinline__ unsigned ld_acquire_gpu(const unsigned* p) {
    unsigned v;
    asm volatile("ld.acquire.gpu.global.u32 %0, [%1];" : "=r"(v) : "l"(p) : "memory");
    return v;
}
__device__ __forceinline__ unsigned ld_relaxed_gpu(const unsigned* p) {
    unsigned v;
    asm volatile("ld.relaxed.gpu.global.u32 %0, [%1];" : "=r"(v) : "l"(p) : "memory");
    return v;
}
__device__ __forceinline__ void red_release_add(unsigned* p, unsigned v) {
    asm volatile("red.release.gpu.global.add.u32 [%0], %1;" :: "l"(p), "r"(v) : "memory");
}

// Max m in [0,7] s.t. windows [pos-k*s, pos-(k-1)*s) are all clean for k<=m.
// tab[c] = min over s chunks starting at c. The 7 loads are independent.
__device__ __forceinline__ int leading_clean7(const float* __restrict__ tab,
                                              int pos, int s, float thr) {
    bool ok = true;
    int m = 0;
#pragma unroll
    for (int k = 1; k <= 7; k++) {
        const int npos = pos - k * s;
        const float v = tab[npos >= 0 ? npos : 0];
        ok = ok && (npos >= 0) && (v >= thr);
        m += ok ? 1 : 0;
    }
    return m;
}

__device__ __forceinline__ float abs4(float4 v) {
    return fabsf(v.x) + fabsf(v.y) + fabsf(v.z) + fabsf(v.w);
}

__global__ void __launch_bounds__(NT, 1) fused_kernel(const float* __restrict__ x,
                                                      float* __restrict__ out) {
    __shared__ float sn_own[QPB];    // this segment's 128 norms
    __shared__ float sL1[NCH];       // chunk minima (prefix + own valid)
    __shared__ float sL8[NCH];       // min over 8 chunks
    __shared__ float sL64[NCH];      // min over 64 chunks

    const int tid  = threadIdx.x;
    const int lane = tid & 31;
    const int warp = tid >> 5;         // 16 warps = 16 chunks of this segment
    const int seg  = blockIdx.x >> 2;  // 0..31 (low segments dispatch first)
    const int b    = blockIdx.x & 3;   // batch row

    // Per-replay target: only THIS block increments flag[b][seg].
    unsigned target = 0;
    if (tid == 0) target = ld_relaxed_gpu(&g_flag[b][seg]) + 1u;

    // ---------- Phase 1: 128 norms + 16 chunk minima for (b, seg) ----------
    // 4 threads per row, 4 back-to-back float4 loads (MLP=4, coalesced 2KB/warp).
    {
        const int rloc = tid >> 2;               // 0..127
        const int q    = tid & 3;
        const int row  = b * S_LEN + seg * QPB + rloc;
        const float4* src = reinterpret_cast<const float4*>(x + (size_t)row * D_DIM) + q * 4;
        const float4 a0 = src[0];
        const float4 a1 = src[1];
        const float4 a2 = src[2];
        const float4 a3 = src[3];
        float s = (abs4(a0) + abs4(a1)) + (abs4(a2) + abs4(a3));
        s += __shfl_xor_sync(0xffffffffu, s, 1);
        s += __shfl_xor_sync(0xffffffffu, s, 2);   // all 4 lanes hold the row sum
        if (q == 0) {
            g_norms[row]  = s;
            sn_own[rloc]  = s;
        }
        // Warp = 8 rows = one chunk; min over the warp (each row 4x, harmless).
        float m = s;
#pragma unroll
        for (int o = 16; o > 0; o >>= 1)
            m = fminf(m, __shfl_xor_sync(0xffffffffu, m, o));
        const int cglob = seg * 16 + warp;
        if (lane == 0) {
            g_L1[b * NCH + cglob] = m;
            sL1[cglob] = m;                        // own entries seeded locally
        }
    }
    __syncthreads();   // order all global stores before the release
    if (tid == 0) red_release_add(&g_flag[b][seg], 1u);

    // ---------- Prefix wait: warp 0 polls flags 0..seg-1 (read-only) --------
    if (tid < 32) {
        const unsigned tgt = __shfl_sync(0xffffffffu, target, 0);
        bool done = lane >= seg;   // need only strictly-earlier segments
        while (!__all_sync(0xffffffffu, done)) {
            if (!done) done = ld_acquire_gpu(&g_flag[b][lane]) >= tgt;
        }
    }
    __syncthreads();   // acquire + bar: prefix g_L1/g_norms now visible

    // ---------- Phase 2: load prefix chunk minima (<=2KB) + build tables ----
    if (tid < seg * 16)
        sL1[tid] = g_L1[b * NCH + tid];
    __syncthreads();

    {   // L8[c] = min over L1[c..c+7]; entries past the valid prefix are
        // garbage but provably never consulted (probed windows end < pos).
        float m = sL1[tid];
#pragma unroll
        for (int k = 1; k < 8; k++) {
            const int idx = tid + k;
            m = fminf(m, sL1[idx < NCH ? idx : NCH - 1]);
        }
        sL8[tid] = m;
    }
    __syncthreads();

    {   // L64[c] = min over 64 chunks = 8 L8 entries at stride 8.
        float m = sL8[tid];
#pragma unroll
        for (int k = 1; k < 8; k++) {
            const int idx = tid + k * 8;
            m = fminf(m, sL8[idx < NCH ? idx : NCH - 1]);
        }
        sL64[tid] = m;
    }
    __syncthreads();

    // ---------- Phase 3: one query per thread (tid < QPB) ----------
    if (tid < QPB) {
        const int t = seg * QPB + tid;               // global position in batch
        const float thr = 0.7f * (sn_own[tid] + 1e-8f);

        // A) partial chunk [cb, t) — own segment, from smem.
        const int cbl = tid & ~(CH - 1);             // local chunk base
        int best = -1;                               // global index of hit
#pragma unroll
        for (int k = 0; k < CH - 1; k++) {
            if (cbl + k < tid && sn_own[cbl + k] < thr) best = seg * QPB + cbl + k;
        }

        // B) 7-ary descend over scales {64,8,1}; C) read dirty chunk from L2.
        if (best < 0 && t >= CH) {
            int pos = t >> 3;                        // global chunk index, >= 1
            pos -= 64 * leading_clean7(sL64, pos, 64, thr);
            pos -= 8  * leading_clean7(sL8,  pos, 8,  thr);
            pos -=      leading_clean7(sL1,  pos, 1,  thr);
            if (pos > 0) {
                const int base = (pos - 1) * CH;     // guaranteed-dirty chunk
                const float4* p = reinterpret_cast<const float4*>(
                    g_norms + (size_t)b * S_LEN + base);
                const float4 v0 = p[0];
                const float4 v1 = p[1];
                const float c[8] = {v0.x, v0.y, v0.z, v0.w, v1.x, v1.y, v1.z, v1.w};
#pragma unroll
                for (int k = 0; k < CH; k++)
                    if (c[k] < thr) best = base + k;
            }
        }

        out[(size_t)b * S_LEN + t] = best >= 0 ? (float)(t - best) : 0.0f;
    }
}

// ---------------------------------------------------------------------------
// Launch: single fused kernel, 128 blocks x 512 threads.
// ---------------------------------------------------------------------------
extern "C" void kernel_launch(void* const* d_in, const int* in_sizes, int n_in,
                              void* d_out, int out_size) {
    const float* x = (const float*)d_in[0];
    float* out = (float*)d_out;
    fused_kernel<<<NB, NT>>>(x, out);
}

// round 13
// speedup vs baseline: 1.0369x; 1.0369x over previous
#include <cuda_runtime.h>

// Problem shape (fixed by setup_inputs): x: (B=4, S=4096, D=64) f32; out: (B,S) f32
#define S_LEN  4096
#define D_DIM  64
#define CH     8               // chunk size (norm elements per L1 entry)
#define NCH    (S_LEN / CH)    // 512 chunks per row
#define NB     128             // grid (co-resident: 128 <= 148 SMs)
#define NT     512             // threads per block
#define QPB    128             // queries/rows per block (32 segments per batch row)

// Device-global scratch (no allocation). Flags are MONOTONIC across graph
// replays (one producer per flag, +1 per launch; per-replay target derived
// from the producer's own flag value at entry).
__device__ float    g_norms[4 * S_LEN];
__device__ unsigned g_flag[4][32];     // flag[b][s]: segment s of batch b done

__device__ __forceinline__ unsigned ld_acquire_gpu(const unsigned* p) {
    unsigned v;
    asm volatile("ld.acquire.gpu.global.u32 %0, [%1];" : "=r"(v) : "l"(p) : "memory");
    return v;
}
__device__ __forceinline__ unsigned ld_relaxed_gpu(const unsigned* p) {
    unsigned v;
    asm volatile("ld.relaxed.gpu.global.u32 %0, [%1];" : "=r"(v) : "l"(p) : "memory");
    return v;
}
__device__ __forceinline__ void red_release_add(unsigned* p, unsigned v) {
    asm volatile("red.release.gpu.global.add.u32 [%0], %1;" :: "l"(p), "r"(v) : "memory");
}

// Max m in [0,7] s.t. windows [pos-k*s, pos-(k-1)*s) are all clean for k<=m.
// tab[c] = min over s chunks starting at c. The 7 loads are independent.
__device__ __forceinline__ int leading_clean7(const float* __restrict__ tab,
                                              int pos, int s, float thr) {
    bool ok = true;
    int m = 0;
#pragma unroll
    for (int k = 1; k <= 7; k++) {
        const int npos = pos - k * s;
        const float v = tab[npos >= 0 ? npos : 0];
        ok = ok && (npos >= 0) && (v >= thr);
        m += ok ? 1 : 0;
    }
    return m;
}

__device__ __forceinline__ float abs4(float4 v) {
    return fabsf(v.x) + fabsf(v.y) + fabsf(v.z) + fabsf(v.w);
}
__device__ __forceinline__ float min8(float4 a, float4 b) {
    return fminf(fminf(fminf(a.x, a.y), fminf(a.z, a.w)),
                 fminf(fminf(b.x, b.y), fminf(b.z, b.w)));
}

__global__ void __launch_bounds__(NT, 1) fused_kernel(const float* __restrict__ x,
                                                      float* __restrict__ out) {
    __shared__ float sn[S_LEN];      // norms: own segment (phase1) + prefix (staged)
    __shared__ float sL1[NCH];       // min over 1 chunk  (8 elems)
    __shared__ float sL8[NCH];       // min over 8 chunks
    __shared__ float sL64[NCH];      // min over 64 chunks

    const int tid  = threadIdx.x;
    const int lane = tid & 31;
    const int seg  = blockIdx.x >> 2;  // 0..31 (low segments dispatch first)
    const int b    = blockIdx.x & 3;   // batch row

    // Per-replay target: only THIS block increments flag[b][seg].
    unsigned target = 0;
    if (tid == 0) target = ld_relaxed_gpu(&g_flag[b][seg]) + 1u;

    // ---------- Phase 1: norms for segment (b, seg): 128 rows ----------
    // 4 threads per row, 4 back-to-back float4 loads (MLP=4, coalesced 2KB/warp).
    {
        const int rloc = tid >> 2;               // 0..127
        const int q    = tid & 3;
        const int row  = b * S_LEN + seg * QPB + rloc;
        const float4* src = reinterpret_cast<const float4*>(x + (size_t)row * D_DIM) + q * 4;
        const float4 a0 = src[0];
        const float4 a1 = src[1];
        const float4 a2 = src[2];
        const float4 a3 = src[3];
        float s = (abs4(a0) + abs4(a1)) + (abs4(a2) + abs4(a3));
        s += __shfl_xor_sync(0xffffffffu, s, 1);
        s += __shfl_xor_sync(0xffffffffu, s, 2);
        if (q == 0) {
            g_norms[row] = s;
            sn[seg * QPB + rloc] = s;            // own segment lives in smem
        }
    }
    __syncthreads();   // order stores (global + smem) before release / phase A
    if (tid == 0) red_release_add(&g_flag[b][seg], 1u);   // publish segment

    // ---------- Overlap window: warp 0 polls; query warps do phase A --------
    // Queries live on warps 12..15 (tid 384..511), qid = tid-384, t = seg*128+qid.
    int   t = 0, bestA = -1;
    float thr = 0.0f;
    if (tid >= 384) {
        const int qid = tid - 384;
        t   = seg * QPB + qid;
        thr = 0.7f * (sn[t] + 1e-8f);
        // Partial chunk [t&~7, t): 8|128 so it's entirely in the own segment.
        const int cb = t & ~(CH - 1);
#pragma unroll
        for (int k = 0; k < CH - 1; k++) {
            const int j = cb + k;
            if (j < t && sn[j] < thr) bestA = j;  // ascending keeps max j
        }
    }
    if (tid < 32) {   // prefix wait: read-only acquire poll on flags 0..seg-1
        const unsigned tgt = __shfl_sync(0xffffffffu, target, 0);
        bool done = lane >= seg;
        while (!__all_sync(0xffffffffu, done)) {
            if (!done) done = ld_acquire_gpu(&g_flag[b][lane]) >= tgt;
        }
    }
    __syncthreads();   // acquire + bar: prefix g_norms now visible

    // ---------- Stage prefix norms + build L1 (1 chunk per thread) ----------
    // Valid chunk region is [0, (seg+1)*16); entries above are garbage but
    // provably never consulted (all probed windows end < pos <= chunk(t)).
    if (tid < seg * 16) {                         // prefix chunk from L2
        const float4* p = reinterpret_cast<const float4*>(g_norms + (size_t)b * S_LEN) + 2 * tid;
        const float4 a0 = p[0];
        const float4 a1 = p[1];
        float4* dst = reinterpret_cast<float4*>(sn);
        dst[2 * tid + 0] = a0;
        dst[2 * tid + 1] = a1;
        sL1[tid] = min8(a0, a1);
    } else if (tid < (seg + 1) * 16) {            // own-segment chunk from smem
        const float4* p = reinterpret_cast<const float4*>(sn) + 2 * tid;
        sL1[tid] = min8(p[0], p[1]);
    }
    __syncthreads();

    {   // L8[c] = min over L1[c..c+7]
        float m = sL1[tid];
#pragma unroll
        for (int k = 1; k < 8; k++) {
            const int idx = tid + k;
            m = fminf(m, sL1[idx < NCH ? idx : NCH - 1]);
        }
        sL8[tid] = m;
    }
    __syncthreads();

    {   // L64[c] = min over 64 chunks = 8 L8 entries at stride 8
        float m = sL8[tid];
#pragma unroll
        for (int k = 1; k < 8; k++) {
            const int idx = tid + k * 8;
            m = fminf(m, sL8[idx < NCH ? idx : NCH - 1]);
        }
        sL64[tid] = m;
    }
    __syncthreads();

    // ---------- Phase 3: descend + resolve (query warps) ----------
    if (tid >= 384) {
        int best = bestA;
        if (best < 0 && t >= CH) {
            int pos = t >> 3;                        // global chunk index, >= 1
            pos -= 64 * leading_clean7(sL64, pos, 64, thr);
            pos -= 8  * leading_clean7(sL8,  pos, 8,  thr);
            pos -=      leading_clean7(sL1,  pos, 1,  thr);
            if (pos > 0) {
                const int base = (pos - 1) * CH;     // guaranteed-dirty chunk (in smem)
#pragma unroll
                for (int k = 0; k < CH; k++)
                    if (sn[base + k] < thr) best = base + k;
            }
        }
        out[(size_t)b * S_LEN + t] = best >= 0 ? (float)(t - best) : 0.0f;
    }
}

// ---------------------------------------------------------------------------
// Launch: single fused kernel, 128 blocks x 512 threads.
// ---------------------------------------------------------------------------
extern "C" void kernel_launch(void* const* d_in, const int* in_sizes, int n_in,
                              void* d_out, int out_size) {
    const float* x = (const float*)d_in[0];
    float* out = (float*)d_out;
    fused_kernel<<<NB, NT>>>(x, out);
}